// round 16
// baseline (speedup 1.0000x reference)
#include <cuda_runtime.h>
#include <cuda_fp16.h>
#include <math.h>
#include <stdint.h>

// Problem constants
#define B_SZ    512
#define DFEAT   2048
#define DATTR   312
#define DATTR_P 320              // N padded to 4*80
#define NCLS_P  152              // class table stride
#define WSCALE  64.0f            // W pre-scale (exact power of 2)
#define WINV    0.015625f        // 1/64

// GEMM tiling: D[512,320] = X[512,2048] @ W^T, fp16 hi/lo 4-product split
#define MT_BLK  128              // M per CTA
#define NT_BLK  80               // N per CTA
#define BKT     32               // K per smem tile
#define KSPLIT  8
#define KSLICE  (DFEAT / KSPLIT) // 256
#define NCTA    128              // one wave, co-resident (<=148 SMs)
#define NTHR    512              // 16 warps/SM: 2x latency hiding vs 8

// Scratch (__device__ globals: allocation-free, zero-initialized)
__device__ __half g_WhiT[DATTR_P * DFEAT];   // (64*W)^T K-major; rows >=312 stay 0
__device__ __half g_WloT[DATTR_P * DFEAT];
__device__ float g_partial[KSPLIT][B_SZ][DATTR_P];
__device__ float g_Sf[B_SZ];
__device__ unsigned int g_bar0;   // phase0 -> gemm barrier    (reset in tail)
__device__ unsigned int g_bar1;   // gemm  -> rowstats barrier (reset in tail)
__device__ unsigned int g_done;   // rowstats -> tail counter  (reset in tail)

__device__ __forceinline__ void grid_barrier(unsigned int* ctr)
{
    __threadfence();
    __syncthreads();
    if (threadIdx.x == 0) {
        atomicAdd(ctr, 1u);
        while (*(volatile unsigned int*)ctr < (unsigned)NCTA) { }
    }
    __syncthreads();
}

__device__ __forceinline__ uint32_t pack2(float a, float b)
{
    const __half2 h = __halves2half2(__float2half_rn(a), __float2half_rn(b));
    return *(const uint32_t*)&h;
}

// ---------------------------------------------------------------------------
// THE kernel. grid 128 CTAs (co-resident), 512 threads (16 warps).
// phase0: W*64 -> fp16 hi/lo transpose | barrier | GEMM (4 fp16 products)
// | barrier | rowstats (4 rows/CTA) | last-CTA pair-loss tail.
// ---------------------------------------------------------------------------
__global__ __launch_bounds__(NTHR) void fused_kernel(
    const float* __restrict__ X,     // [512, 2048]
    const float* __restrict__ Wm,    // [2048, 312]
    const float* __restrict__ bvec,  // [312]
    const int*   __restrict__ labw,  // [512] labels (int32 or int64 words)
    float*       __restrict__ out)
{
    const int tid  = threadIdx.x;
    const int bid  = blockIdx.x;
    const int wid  = tid >> 5;
    const int lane = tid & 31;

    // ================= phase 0: W split (grid-stride over 320 tiles) =======
    {
        __shared__ __align__(16) float tw[64][33];
        for (int t = bid; t < 320; t += NCTA) {
            const int n0 = (t % 10) * 32, k0 = (t / 10) * 64;
            if (tid < 256) {
                const int r = tid >> 2, q = tid & 3;
                #pragma unroll
                for (int h = 0; h < 2; h++) {
                    const int qq = q + 4 * h;
                    const int n = n0 + qq * 4;
                    const float4 v = (n < DATTR)
                        ? *(const float4*)(Wm + (size_t)(k0 + r) * DATTR + n)
                        : make_float4(0.f, 0.f, 0.f, 0.f);
                    tw[r][qq * 4 + 0] = v.x;
                    tw[r][qq * 4 + 1] = v.y;
                    tw[r][qq * 4 + 2] = v.z;
                    tw[r][qq * 4 + 3] = v.w;
                }
            }
            __syncthreads();
            if (tid < 256) {
                const int nl = tid >> 3, kc = tid & 7;
                const int n = n0 + nl;
                if (n < DATTR) {
                    float vf[8], hf[8];
                    uint32_t hw[4], lw[4];
                    #pragma unroll
                    for (int j = 0; j < 8; j++) {
                        vf[j] = tw[kc * 8 + j][nl] * WSCALE;
                        hf[j] = __half2float(__float2half_rn(vf[j]));
                    }
                    #pragma unroll
                    for (int j = 0; j < 4; j++) {
                        hw[j] = pack2(hf[2 * j], hf[2 * j + 1]);
                        lw[j] = pack2(vf[2 * j] - hf[2 * j], vf[2 * j + 1] - hf[2 * j + 1]);
                    }
                    const size_t off = (size_t)n * DFEAT + k0 + kc * 8;
                    *(uint4*)(g_WhiT + off) = make_uint4(hw[0], hw[1], hw[2], hw[3]);
                    *(uint4*)(g_WloT + off) = make_uint4(lw[0], lw[1], lw[2], lw[3]);
                }
            }
            __syncthreads();
        }
    }
    grid_barrier(&g_bar0);

    // ================= phase 1: GEMM ========================================
    {
        __shared__ __align__(16) __half sAhi[MT_BLK][40];
        __shared__ __align__(16) __half sAlo[MT_BLK][40];
        __shared__ __align__(16) __half sBhi[NT_BLK][40];
        __shared__ __align__(16) __half sBlo[NT_BLK][40];

        const int nt = bid & 3;
        const int mt = (bid >> 2) & 3;
        const int zs = bid >> 4;          // 0..7

        const int warpM = wid >> 1;       // 0..7  (16 rows each)
        const int warpN = wid & 1;        // 0..1  (40 cols each)
        const int mBase = mt * MT_BLK;
        const int nBase = nt * NT_BLK;
        const int k0    = zs * KSLICE;

        const int lq = lane >> 2;
        const int lr = lane & 3;

        // fill roles: A = 1024 float4/tile -> 2 per thread; B = 320 uint4 -> tid<320
        float4 xa[2];
        uint4  wh, wl;
        const bool bown = (tid < 320);
        const int  wrow = tid >> 2, wc = tid & 3;

        float acc[5][4] = {};

        {
            const int k = k0;
            #pragma unroll
            for (int it = 0; it < 2; it++) {
                const int idx = tid + NTHR * it;
                xa[it] = *(const float4*)(X + (size_t)(mBase + (idx >> 3)) * DFEAT + k + (idx & 7) * 4);
            }
            if (bown) {
                wh = *(const uint4*)(g_WhiT + (size_t)(nBase + wrow) * DFEAT + k + wc * 8);
                wl = *(const uint4*)(g_WloT + (size_t)(nBase + wrow) * DFEAT + k + wc * 8);
            }
        }

        for (int kt = 0; kt < KSLICE; kt += BKT) {
            #pragma unroll
            for (int it = 0; it < 2; it++) {
                const int idx = tid + NTHR * it;
                const int row = idx >> 3, ac = idx & 7;
                const float4 v = xa[it];
                const float h0 = __half2float(__float2half_rn(v.x));
                const float h1 = __half2float(__float2half_rn(v.y));
                const float h2 = __half2float(__float2half_rn(v.z));
                const float h3 = __half2float(__float2half_rn(v.w));
                *(uint32_t*)&sAhi[row][ac * 4]     = pack2(h0, h1);
                *(uint32_t*)&sAhi[row][ac * 4 + 2] = pack2(h2, h3);
                *(uint32_t*)&sAlo[row][ac * 4]     = pack2(v.x - h0, v.y - h1);
                *(uint32_t*)&sAlo[row][ac * 4 + 2] = pack2(v.z - h2, v.w - h3);
            }
            if (bown) {
                *(uint4*)&sBhi[wrow][wc * 8] = wh;
                *(uint4*)&sBlo[wrow][wc * 8] = wl;
            }
            __syncthreads();

            if (kt + BKT < KSLICE) {
                const int k = k0 + kt + BKT;
                #pragma unroll
                for (int it = 0; it < 2; it++) {
                    const int idx = tid + NTHR * it;
                    xa[it] = *(const float4*)(X + (size_t)(mBase + (idx >> 3)) * DFEAT + k + (idx & 7) * 4);
                }
                if (bown) {
                    wh = *(const uint4*)(g_WhiT + (size_t)(nBase + wrow) * DFEAT + k + wc * 8);
                    wl = *(const uint4*)(g_WloT + (size_t)(nBase + wrow) * DFEAT + k + wc * 8);
                }
            }

            #pragma unroll
            for (int kk = 0; kk < BKT; kk += 16) {
                uint32_t ahi[4], alo[4];
                {
                    const int r = warpM * 16 + lq;
                    ahi[0] = *(const uint32_t*)&sAhi[r    ][kk + lr * 2    ];
                    ahi[1] = *(const uint32_t*)&sAhi[r + 8][kk + lr * 2    ];
                    ahi[2] = *(const uint32_t*)&sAhi[r    ][kk + lr * 2 + 8];
                    ahi[3] = *(const uint32_t*)&sAhi[r + 8][kk + lr * 2 + 8];
                    alo[0] = *(const uint32_t*)&sAlo[r    ][kk + lr * 2    ];
                    alo[1] = *(const uint32_t*)&sAlo[r + 8][kk + lr * 2    ];
                    alo[2] = *(const uint32_t*)&sAlo[r    ][kk + lr * 2 + 8];
                    alo[3] = *(const uint32_t*)&sAlo[r + 8][kk + lr * 2 + 8];
                }
                uint32_t bhi[5][2], blo[5][2];
                #pragma unroll
                for (int bn = 0; bn < 5; bn++) {
                    const int n = warpN * 40 + bn * 8 + lq;
                    bhi[bn][0] = *(const uint32_t*)&sBhi[n][kk + lr * 2    ];
                    bhi[bn][1] = *(const uint32_t*)&sBhi[n][kk + lr * 2 + 8];
                    blo[bn][0] = *(const uint32_t*)&sBlo[n][kk + lr * 2    ];
                    blo[bn][1] = *(const uint32_t*)&sBlo[n][kk + lr * 2 + 8];
                }
                #pragma unroll
                for (int bn = 0; bn < 5; bn++) {
                    float* c = acc[bn];
                    #define MMA(AV, BV)                                             \
                        asm volatile(                                                \
                            "mma.sync.aligned.m16n8k16.row.col.f32.f16.f16.f32 "    \
                            "{%0,%1,%2,%3}, {%4,%5,%6,%7}, {%8,%9}, {%0,%1,%2,%3};" \
                            : "+f"(c[0]), "+f"(c[1]), "+f"(c[2]), "+f"(c[3])         \
                            : "r"(AV[0]), "r"(AV[1]), "r"(AV[2]), "r"(AV[3]),        \
                              "r"(BV[0]), "r"(BV[1]))
                    MMA(ahi, bhi[bn]);   // hi*hi
                    MMA(ahi, blo[bn]);   // hi*lo
                    MMA(alo, bhi[bn]);   // lo*hi
                    MMA(alo, blo[bn]);   // lo*lo (MMAs are cheap: keep accuracy)
                    #undef MMA
                }
            }
            __syncthreads();
        }

        // epilogue: un-scale (W was *64) and write fp32 partials
        {
            const int row0 = mBase + warpM * 16 + lq;
            #pragma unroll
            for (int bn = 0; bn < 5; bn++) {
                const int col = nBase + warpN * 40 + bn * 8 + lr * 2;
                *(float2*)&g_partial[zs][row0    ][col] =
                    make_float2(acc[bn][0] * WINV, acc[bn][1] * WINV);
                *(float2*)&g_partial[zs][row0 + 8][col] =
                    make_float2(acc[bn][2] * WINV, acc[bn][3] * WINV);
            }
        }
    }
    grid_barrier(&g_bar1);

    // ================= phase 2: rowstats, 4 rows per CTA =================
    {
        __shared__ __align__(16) float vhalf[2][DATTR_P];
        __shared__ __align__(16) float vals[DATTR_P];
        __shared__ float sred[16], sse[16], srs[16];

        for (int r = 0; r < 4; r++) {
            const int i = bid * 4 + r;

            if (tid < 160) {
                const int half = (tid < 80) ? 0 : 1;
                const int c4   = (tid < 80) ? tid : (tid - 80);
                float4 a = make_float4(0.f, 0.f, 0.f, 0.f);
                #pragma unroll
                for (int s = 0; s < 4; s++) {
                    const float4 p = __ldcg((const float4*)&g_partial[half * 4 + s][i][c4 * 4]);
                    a.x += p.x; a.y += p.y; a.z += p.z; a.w += p.w;
                }
                *(float4*)&vhalf[half][c4 * 4] = a;
            }
            __syncthreads();
            if (tid < 80) {
                float4 a = *(const float4*)&vhalf[0][tid * 4];
                const float4 c = *(const float4*)&vhalf[1][tid * 4];
                const float4 bb = (tid < 78) ? *(const float4*)(bvec + tid * 4)
                                             : make_float4(0.f, 0.f, 0.f, 0.f);
                a.x += c.x + bb.x; a.y += c.y + bb.y;
                a.z += c.z + bb.z; a.w += c.w + bb.w;
                *(float4*)&vals[tid * 4] = a;
            }
            __syncthreads();

            float m = -1e30f;
            for (int c = tid; c < DATTR; c += NTHR) m = fmaxf(m, vals[c]);
            #pragma unroll
            for (int o = 16; o; o >>= 1) m = fmaxf(m, __shfl_xor_sync(0xffffffffu, m, o));
            if (lane == 0) sred[wid] = m;
            __syncthreads();
            m = sred[0];
            #pragma unroll
            for (int w = 1; w < 16; w++) m = fmaxf(m, sred[w]);

            float se = 0.f, rs = 0.f;
            for (int c = tid; c < DATTR; c += NTHR) {
                const float v = vals[c];
                se += expf(v - m);
                rs += v;
            }
            #pragma unroll
            for (int o = 16; o; o >>= 1) {
                se += __shfl_xor_sync(0xffffffffu, se, o);
                rs += __shfl_xor_sync(0xffffffffu, rs, o);
            }
            if (lane == 0) { sse[wid] = se; srs[wid] = rs; }
            __syncthreads();

            if (tid == 0) {
                float seT = 0.f, rsT = 0.f;
                #pragma unroll
                for (int w = 0; w < 16; w++) { seT += sse[w]; rsT += srs[w]; }
                g_Sf[i] = rsT - (float)DATTR * (m + logf(seT));
            }
            __syncthreads();
        }
    }

    // ================= tail: last CTA computes the pair loss =================
    __shared__ int s_last;
    __threadfence();
    if (tid == 0) {
        const unsigned int old = atomicAdd(&g_done, 1u);
        s_last = (old == (unsigned int)(NCTA - 1));
    }
    __syncthreads();
    if (!s_last) return;

    __shared__ int           table[16][NCLS_P];
    __shared__ int           s_not64;
    __shared__ double        swsum[16];
    __shared__ unsigned int  swcnt[16];

    if (tid == 0) s_not64 = 0;
    for (int idx = tid; idx < 16 * NCLS_P; idx += NTHR)
        ((int*)table)[idx] = 0;
    __syncthreads();

    // label dtype sniff: int64 buffers have zero odd words (labels < 150)
    if (tid < 256 && labw[2 * tid + 1] != 0) atomicOr(&s_not64, 1);
    __syncthreads();
    const bool is64 = (s_not64 == 0);

    const int li = is64 ? labw[2 * tid] : labw[tid];
    atomicAdd(&table[wid][li], 1);
    __syncthreads();

    const unsigned lt = (1u << lane) - 1u;
    const unsigned mm = __match_any_sync(0xffffffffu, li);

    int rank = __popc(mm & lt), all = 0;
    #pragma unroll
    for (int w = 0; w < 16; w++) {
        const int c = table[w][li];
        all += c;
        if (w < wid) rank += c;
    }

    // loss_sum = sum_t coef_t*(S_t - S_0), coef_t = 2*rank+1-cnt_all.
    // sum(coef)=0 per class => shift exact; double dot kills cancellation.
    const float ref = __ldcg(&g_Sf[0]);
    double local = (double)(2 * rank + 1 - all) *
                   (double)(__ldcg(&g_Sf[tid]) - ref);
    unsigned int cnt = (unsigned int)rank;

    #pragma unroll
    for (int o = 16; o; o >>= 1) {
        local += __shfl_xor_sync(0xffffffffu, local, o);
        cnt   += __shfl_xor_sync(0xffffffffu, cnt, o);
    }
    if (lane == 0) { swsum[wid] = local; swcnt[wid] = cnt; }
    __syncthreads();

    if (tid == 0) {
        double s = 0.0; unsigned int c = 0;
        #pragma unroll
        for (int w = 0; w < 16; w++) { s += swsum[w]; c += swcnt[w]; }
        out[0] = (float)((c > 0) ? (s / (double)c) : s);
        g_done = 0;   // reset all counters for the next graph replay
        g_bar0 = 0;
        g_bar1 = 0;
    }
}

// ---------------------------------------------------------------------------
extern "C" void kernel_launch(void* const* d_in, const int* in_sizes, int n_in,
                              void* d_out, int out_size)
{
    const float* x   = (const float*)d_in[0];      // [512, 2048]
    const float* Wm  = (const float*)d_in[1];      // [2048, 312]
    const float* b   = (const float*)d_in[2];      // [312]
    // d_in[3] = seen_att : unused (cancels exactly for same-label pairs)
    const int*   lab = (const int*)d_in[4];        // [512] labels

    fused_kernel<<<NCTA, NTHR>>>(x, Wm, b, lab, (float*)d_out);
}